// round 7
// baseline (speedup 1.0000x reference)
#include <cuda_runtime.h>
#include <cuda_bf16.h>
#include <cstdint>

// Problem constants
#define KC  8192          // number of codes
#define DD  256           // embedding / channel dim
#define NR  16384         // B*H*W rows
#define HW  1024          // H*W
#define CHW (DD * HW)     // per-batch stride in z / out

#define CAPM    32        // candidate list capacity per row
#define MARGIN  1e-3f     // >= 2x worst-case bf16 score error (~5.6e-4)

// Scratch (static device memory)
__device__ float g_codebook[KC * DD];        // emb @ proj_w^T fp32
__device__ float g_zf[NR * DD];              // z transposed [N][D] fp32
__device__ float g_zn[NR];                   // ||z_n||^2 (fp32 chain)
__device__ int   g_cand[NR * CAPM];          // candidate indices
__device__ int   g_cand_cnt[NR];             // count (>CAPM = overflow)
__device__ int   g_minidx[NR];
__device__ float g_partials[512];

// Pre-packed bf16 MMA fragments (16B-aligned for cp.async)
// B (codebook): 64 chunks x 64KB. Within chunk: [ks 0..15][nb 0..15][lane 0..31] uint2
__device__ uint4 g_cbp[KC * DD * 2 / 16];
// A (z): 128 bands x 64KB. Within band: [rb 0..7][ks 0..15][lane 0..31] uint4
__device__ uint4 g_zp[NR * DD * 2 / 16];

// ---------------- helpers ----------------
__device__ __forceinline__ uint32_t bf16pack(float lo, float hi) {
    uint32_t l = (uint32_t)__bfloat16_as_ushort(__float2bfloat16(lo));
    uint32_t h = (uint32_t)__bfloat16_as_ushort(__float2bfloat16(hi));
    return (h << 16) | l;
}
__device__ __forceinline__ uint32_t smem_u32(const void* p) {
    uint32_t a;
    asm("{ .reg .u64 t; cvta.to.shared.u64 t, %1; cvt.u32.u64 %0, t; }"
        : "=r"(a) : "l"(p));
    return a;
}
__device__ __forceinline__ void cp_async16(uint32_t saddr, const void* g) {
    asm volatile("cp.async.cg.shared.global [%0], [%1], 16;"
                 :: "r"(saddr), "l"(g) : "memory");
}
#define CP_COMMIT() asm volatile("cp.async.commit_group;" ::: "memory")
#define CP_WAIT0()  asm volatile("cp.async.wait_group 0;" ::: "memory")

// m16n8k16 row.col bf16 -> fp32 accumulate
__device__ __forceinline__ void mma16816(float& c0, float& c1, float& c2, float& c3,
                                         uint32_t a0, uint32_t a1, uint32_t a2, uint32_t a3,
                                         uint32_t b0, uint32_t b1) {
    asm volatile("mma.sync.aligned.m16n8k16.row.col.f32.bf16.bf16.f32 "
                 "{%0,%1,%2,%3}, {%4,%5,%6,%7}, {%8,%9}, {%0,%1,%2,%3};"
                 : "+f"(c0), "+f"(c1), "+f"(c2), "+f"(c3)
                 : "r"(a0), "r"(a1), "r"(a2), "r"(a3), "r"(b0), "r"(b1));
}

// ---------------------------------------------------------------------------
// Kernel 1: codebook = emb @ proj^T (exact fp32 sequential-j chain) + fused
// bf16 B-fragment pack into g_cbp.
// B frag (col-major k16xn8): lane=g*4+tig; reg0: d=ks*16+tig*2,+1; reg1: +8.
// ---------------------------------------------------------------------------
__global__ void codebook_gemm(const float* __restrict__ emb,
                              const float* __restrict__ pw) {
    __shared__ float As[16 * 65];
    __shared__ float Bs[16 * 65];
    const int tid = threadIdx.x;
    const int tx = tid & 15, ty = tid >> 4;
    const int k0 = blockIdx.y * 64;
    const int d0 = blockIdx.x * 64;
    const int rl = tid >> 2;
    const int j4 = (tid & 3) << 2;

    float acc[4][4];
#pragma unroll
    for (int u = 0; u < 4; u++)
#pragma unroll
        for (int v = 0; v < 4; v++) acc[u][v] = 0.f;

    for (int j0 = 0; j0 < DD; j0 += 16) {
        float4 va = *(const float4*)&emb[(k0 + rl) * DD + j0 + j4];
        float4 vb = *(const float4*)&pw[(d0 + rl) * DD + j0 + j4];
        As[(j4 + 0) * 65 + rl] = va.x;  As[(j4 + 1) * 65 + rl] = va.y;
        As[(j4 + 2) * 65 + rl] = va.z;  As[(j4 + 3) * 65 + rl] = va.w;
        Bs[(j4 + 0) * 65 + rl] = vb.x;  Bs[(j4 + 1) * 65 + rl] = vb.y;
        Bs[(j4 + 2) * 65 + rl] = vb.z;  Bs[(j4 + 3) * 65 + rl] = vb.w;
        __syncthreads();
#pragma unroll
        for (int jj = 0; jj < 16; jj++) {
            const float* ap = &As[jj * 65 + ty * 4];
            const float* bp = &Bs[jj * 65 + tx * 4];
            float a0 = ap[0], a1 = ap[1], a2 = ap[2], a3 = ap[3];
            float b0 = bp[0], b1 = bp[1], b2 = bp[2], b3 = bp[3];
            acc[0][0] = fmaf(a0, b0, acc[0][0]); acc[0][1] = fmaf(a0, b1, acc[0][1]);
            acc[0][2] = fmaf(a0, b2, acc[0][2]); acc[0][3] = fmaf(a0, b3, acc[0][3]);
            acc[1][0] = fmaf(a1, b0, acc[1][0]); acc[1][1] = fmaf(a1, b1, acc[1][1]);
            acc[1][2] = fmaf(a1, b2, acc[1][2]); acc[1][3] = fmaf(a1, b3, acc[1][3]);
            acc[2][0] = fmaf(a2, b0, acc[2][0]); acc[2][1] = fmaf(a2, b1, acc[2][1]);
            acc[2][2] = fmaf(a2, b2, acc[2][2]); acc[2][3] = fmaf(a2, b3, acc[2][3]);
            acc[3][0] = fmaf(a3, b0, acc[3][0]); acc[3][1] = fmaf(a3, b1, acc[3][1]);
            acc[3][2] = fmaf(a3, b2, acc[3][2]); acc[3][3] = fmaf(a3, b3, acc[3][3]);
        }
        __syncthreads();
    }
    char* cbp = (char*)g_cbp;
#pragma unroll
    for (int u = 0; u < 4; u++) {
        int k = k0 + ty * 4 + u;
        float4 w = make_float4(acc[u][0], acc[u][1], acc[u][2], acc[u][3]);
        *(float4*)&g_codebook[k * DD + d0 + tx * 4] = w;
        // bf16 B-fragment pack (two bf16x2 pairs per code)
        int cchunk = k >> 7, nb = (k >> 3) & 15, gg = k & 7;
#pragma unroll
        for (int p = 0; p < 2; p++) {
            int dval = d0 + tx * 4 + p * 2;
            int rem = dval & 15;
            int reg = (rem >= 8) ? 1 : 0;
            int tg  = (rem & 7) >> 1;
            int ks  = dval >> 4;
            uint32_t val = bf16pack(acc[u][p * 2], acc[u][p * 2 + 1]);
            size_t off = (size_t)cchunk * 65536 +
                         (size_t)(((ks * 16 + nb) * 32 + gg * 4 + tg) * 8) + reg * 4;
            *(uint32_t*)(cbp + off) = val;
        }
    }
}

// ---------------------------------------------------------------------------
// Kernel 2: z transpose -> g_zf [N][D] fp32, zn per row, fused A-fragment
// bf16 pack into g_zp.
// A frag (row-major m16xk16): lane=g*4+tig; R0:(row g, d=ks*16+tig*2,+1)
// R1:(row g+8, same d) R2:(row g, d+8) R3:(row g+8, d+8).
// ---------------------------------------------------------------------------
__global__ void z_prep(const float* __restrict__ z) {
    __shared__ float Zs[256 * 33];
    const int tid = threadIdx.x;
    const int n0 = blockIdx.x * 32;
    const int b = n0 >> 10, hw0 = n0 & 1023;
    const float* zb = z + b * CHW + hw0;

    for (int e = tid; e < 32 * DD; e += 256) {
        int d = e >> 5, m = e & 31;
        Zs[d * 33 + m] = zb[d * HW + m];
    }
    __syncthreads();
    // fp32 transposed copy for rescue
    for (int idx = tid; idx < 32 * DD; idx += 256) {
        int nl = idx >> 8, d = idx & 255;
        g_zf[(n0 + nl) * DD + d] = Zs[d * 33 + nl];
    }
    // A-fragment pack
    char* zp = (char*)g_zp;
    for (int idx = tid; idx < 32 * 128; idx += 256) {
        int nl = idx >> 7, p = idx & 127;
        int dval = p * 2;
        float v0 = Zs[dval * 33 + nl];
        float v1 = Zs[(dval + 1) * 33 + nl];
        int n = n0 + nl;
        int band = n >> 7, r = n & 127;
        int rb = r >> 4, r16 = r & 15, gg = r16 & 7;
        int rem = dval & 15;
        int reg = ((r16 >= 8) ? 1 : 0) + ((rem >= 8) ? 2 : 0);
        int tg  = (rem & 7) >> 1;
        int ks  = dval >> 4;
        uint32_t val = bf16pack(v0, v1);
        size_t off = (size_t)band * 65536 +
                     (size_t)(((rb * 16 + ks) * 32 + gg * 4 + tg) * 16) + reg * 4;
        *(uint32_t*)(zp + off) = val;
    }
    if (tid < 32) {
        float s = 0.f;
#pragma unroll 8
        for (int d = 0; d < DD; d++) { float v = Zs[d * 33 + tid]; s = fmaf(v, v, s); }
        g_zn[n0 + tid] = s;
    }
}

// ---------------------------------------------------------------------------
// Kernel 3: HMMA (mma.sync bf16) distance GEMM + margin candidate collect.
// CTA = 128 rows; 8 warps (4 row x 2 col); warp tile 32x64; 64 chunks of
// 128 codes, B double-buffered via cp.async.
// ---------------------------------------------------------------------------
#define SM_A     0
#define SM_B0    65536
#define SM_B1    131072
#define SM_LIST  196608
#define SM_CNT   (196608 + 128 * CAPM * 4)
#define SM_TOTAL (SM_CNT + 128 * 4)

__global__ __launch_bounds__(256, 1)
void mma_cand(void) {
    extern __shared__ char sm[];
    const uint32_t sbase = smem_u32(sm);
    const int tid = threadIdx.x;
    const int w = tid >> 5, lane = tid & 31;
    const int wr = w >> 1, wc = w & 1;
    const int g = lane >> 2, tig = lane & 3;
    const int n0 = blockIdx.x * 128;

    int*  slist = (int*)(sm + SM_LIST);
    int*  scnt  = (int*)(sm + SM_CNT);
    if (tid < 128) scnt[tid] = 0;

    // preload A (64KB) + B chunk 0 (64KB)
    const char* gA = (const char*)g_zp + (size_t)blockIdx.x * 65536;
    const char* gB = (const char*)g_cbp;
#pragma unroll
    for (int t = 0; t < 16; t++)
        cp_async16(sbase + SM_A + tid * 16 + t * 4096, gA + tid * 16 + t * 4096);
#pragma unroll
    for (int t = 0; t < 16; t++)
        cp_async16(sbase + SM_B0 + tid * 16 + t * 4096, gB + tid * 16 + t * 4096);
    CP_COMMIT();
    CP_WAIT0();
    __syncthreads();

    const int rowb = wr * 32 + g;
    float zn[4];
    zn[0] = g_zn[n0 + rowb];      zn[1] = g_zn[n0 + rowb + 8];
    zn[2] = g_zn[n0 + rowb + 16]; zn[3] = g_zn[n0 + rowb + 24];
    float rm[4] = {3.4e38f, 3.4e38f, 3.4e38f, 3.4e38f};

    const uint4* Au = (const uint4*)(sm + SM_A);

    for (int i = 0; i < 64; i++) {
        if (i + 1 < 64) {
            const char* src = gB + (size_t)(i + 1) * 65536;
            uint32_t dstB = sbase + ((((i + 1) & 1) ? SM_B1 : SM_B0));
#pragma unroll
            for (int t = 0; t < 16; t++)
                cp_async16(dstB + tid * 16 + t * 4096, src + tid * 16 + t * 4096);
            CP_COMMIT();
        }

        const uint2* Bu = (const uint2*)(sm + ((i & 1) ? SM_B1 : SM_B0));
        float c[2][8][4];
#pragma unroll
        for (int rb = 0; rb < 2; rb++)
#pragma unroll
            for (int j = 0; j < 8; j++)
#pragma unroll
                for (int q = 0; q < 4; q++) c[rb][j][q] = 0.f;

#pragma unroll
        for (int ks = 0; ks < 16; ks++) {
            uint4 a0 = Au[((wr * 2 + 0) * 16 + ks) * 32 + lane];
            uint4 a1 = Au[((wr * 2 + 1) * 16 + ks) * 32 + lane];
            uint2 bf[8];
#pragma unroll
            for (int j = 0; j < 8; j++)
                bf[j] = Bu[(ks * 16 + wc * 8 + j) * 32 + lane];
#pragma unroll
            for (int j = 0; j < 8; j++) {
                mma16816(c[0][j][0], c[0][j][1], c[0][j][2], c[0][j][3],
                         a0.x, a0.y, a0.z, a0.w, bf[j].x, bf[j].y);
                mma16816(c[1][j][0], c[1][j][1], c[1][j][2], c[1][j][3],
                         a1.x, a1.y, a1.z, a1.w, bf[j].x, bf[j].y);
            }
        }

        // epilogue: score + margin candidate collection
        const int kbase = i * 128 + wc * 64;
#pragma unroll
        for (int rb = 0; rb < 2; rb++) {
            const int lr0 = wr * 32 + rb * 16 + g;
            const float za = zn[rb * 2], zbn = zn[rb * 2 + 1];
#pragma unroll
            for (int j = 0; j < 8; j++) {
                int kc = kbase + j * 8 + tig * 2;
                float s0 = fmaf(-2.f, c[rb][j][0], za);
                float s1 = fmaf(-2.f, c[rb][j][1], za);
                float s2 = fmaf(-2.f, c[rb][j][2], zbn);
                float s3 = fmaf(-2.f, c[rb][j][3], zbn);
                if (s0 < rm[rb * 2] + MARGIN) {
                    if (s0 < rm[rb * 2]) rm[rb * 2] = s0;
                    int sl = atomicAdd(&scnt[lr0], 1);
                    if (sl < CAPM) slist[lr0 * CAPM + sl] = kc;
                }
                if (s1 < rm[rb * 2] + MARGIN) {
                    if (s1 < rm[rb * 2]) rm[rb * 2] = s1;
                    int sl = atomicAdd(&scnt[lr0], 1);
                    if (sl < CAPM) slist[lr0 * CAPM + sl] = kc + 1;
                }
                if (s2 < rm[rb * 2 + 1] + MARGIN) {
                    if (s2 < rm[rb * 2 + 1]) rm[rb * 2 + 1] = s2;
                    int sl = atomicAdd(&scnt[lr0 + 8], 1);
                    if (sl < CAPM) slist[(lr0 + 8) * CAPM + sl] = kc;
                }
                if (s3 < rm[rb * 2 + 1] + MARGIN) {
                    if (s3 < rm[rb * 2 + 1]) rm[rb * 2 + 1] = s3;
                    int sl = atomicAdd(&scnt[lr0 + 8], 1);
                    if (sl < CAPM) slist[(lr0 + 8) * CAPM + sl] = kc + 1;
                }
            }
        }

        if (i + 1 < 64) CP_WAIT0();
        __syncthreads();
    }

    if (tid < 128) {
        int cnt = scnt[tid];
        int n = n0 + tid;
        g_cand_cnt[n] = (cnt > CAPM) ? (CAPM + 1) : cnt;
        int m = (cnt < CAPM) ? cnt : CAPM;
        for (int j = 0; j < m; j++) g_cand[n * CAPM + j] = slist[tid * CAPM + j];
    }
}

// ---------------------------------------------------------------------------
// Kernel 4: exact rescue (bit-exact sequential fp32 chain over candidates).
// ---------------------------------------------------------------------------
__global__ __launch_bounds__(64)
void rescue_kernel(float* __restrict__ idxf) {
    __shared__ float zrow[DD];
    __shared__ float rv[64];
    __shared__ int   ri[64];
    const int n = blockIdx.x;
    const int tid = threadIdx.x;

    *(float4*)&zrow[tid * 4] = *(const float4*)&g_zf[n * DD + tid * 4];
    __syncthreads();
    const float zn = g_zn[n];

    float bv = 3.4e38f; int bi = 0x7FFFFFFF;
    int cnt = g_cand_cnt[n];
    if (cnt > CAPM) {
        for (int k = tid; k < KC; k += 64) {
            float acc = 0.f;
            const float4* cb = (const float4*)&g_codebook[k * DD];
#pragma unroll 4
            for (int d4 = 0; d4 < 64; d4++) {
                float4 cc = cb[d4];
                float4 zv = *(const float4*)&zrow[d4 * 4];
                acc = fmaf(zv.x, cc.x, acc); acc = fmaf(zv.y, cc.y, acc);
                acc = fmaf(zv.z, cc.z, acc); acc = fmaf(zv.w, cc.w, acc);
            }
            float s = fmaf(-2.f, acc, zn);
            if (s < bv || (s == bv && k < bi)) { bv = s; bi = k; }
        }
    } else {
        for (int j = tid; j < cnt; j += 64) {
            int k = g_cand[n * CAPM + j];
            float acc = 0.f;
            const float4* cb = (const float4*)&g_codebook[k * DD];
#pragma unroll 4
            for (int d4 = 0; d4 < 64; d4++) {
                float4 cc = cb[d4];
                float4 zv = *(const float4*)&zrow[d4 * 4];
                acc = fmaf(zv.x, cc.x, acc); acc = fmaf(zv.y, cc.y, acc);
                acc = fmaf(zv.z, cc.z, acc); acc = fmaf(zv.w, cc.w, acc);
            }
            float s = fmaf(-2.f, acc, zn);
            if (s < bv || (s == bv && k < bi)) { bv = s; bi = k; }
        }
    }
    rv[tid] = bv; ri[tid] = bi;
    __syncthreads();
    for (int o = 32; o; o >>= 1) {
        if (tid < o) {
            float v = rv[tid + o]; int i2 = ri[tid + o];
            if (v < rv[tid] || (v == rv[tid] && i2 < ri[tid])) {
                rv[tid] = v; ri[tid] = i2;
            }
        }
        __syncthreads();
    }
    if (tid == 0) {
        g_minidx[n] = ri[0];
        if (idxf) idxf[n] = (float)ri[0];
    }
}

// ---------------------------------------------------------------------------
// Kernel 5: gather + straight-through output + squared error partials.
// out = fl(zt + fl(zq - zt)) exactly as the reference.
// ---------------------------------------------------------------------------
__global__ void gather_out(const float* __restrict__ z, float* __restrict__ out) {
    __shared__ float s[256 * 33];
    const int tid = threadIdx.x;
    const int n0 = blockIdx.x * 32;
    const int b = n0 >> 10, hw0 = n0 & 1023;

#pragma unroll 1
    for (int nl = 0; nl < 32; nl++) {
        int ci = g_minidx[n0 + nl];
        s[tid * 33 + nl] = g_codebook[ci * DD + tid];
    }
    __syncthreads();

    float local = 0.f;
    const float* zb = z + b * CHW + hw0;
    float* ob = out + b * CHW + hw0;
    for (int e = tid; e < 32 * DD; e += 256) {
        int c = e >> 5, hl = e & 31;
        float q  = s[c * 33 + hl];
        float zv = zb[c * HW + hl];
        float d  = q - zv;
        ob[c * HW + hl] = zv + d;
        local = fmaf(d, d, local);
    }
    __syncthreads();
    float* red = s;
    red[tid] = local;
    __syncthreads();
    for (int o = 128; o; o >>= 1) {
        if (tid < o) red[tid] += red[tid + o];
        __syncthreads();
    }
    if (tid == 0) g_partials[blockIdx.x] = red[0];
}

// ---------------------------------------------------------------------------
// Kernel 6: final reduction + loss scalars
// ---------------------------------------------------------------------------
__global__ void finalize_kernel(float* __restrict__ outp, int has_scalars) {
    __shared__ float red[512];
    const int tid = threadIdx.x;
    red[tid] = g_partials[tid];
    __syncthreads();
    for (int o = 256; o; o >>= 1) {
        if (tid < o) red[tid] += red[tid + o];
        __syncthreads();
    }
    if (tid == 0 && has_scalars) {
        float mse = red[0] * (1.0f / 4194304.0f);
        float cl  = 0.25f * mse;
        float bl  = mse;
        outp[4194304] = cl + bl;
        outp[4194305] = cl;
        outp[4194306] = bl;
    }
}

// ---------------------------------------------------------------------------
extern "C" void kernel_launch(void* const* d_in, const int* in_sizes, int n_in,
                              void* d_out, int out_size) {
    const float* z   = (const float*)d_in[0];   // [16,256,32,32]
    const float* emb = (const float*)d_in[1];   // [8192,256]
    const float* pw  = (const float*)d_in[2];   // [256,256]
    float* out = (float*)d_out;

    cudaFuncSetAttribute(mma_cand,
                         cudaFuncAttributeMaxDynamicSharedMemorySize, SM_TOTAL);

    codebook_gemm<<<dim3(4, 128), 256>>>(emb, pw);
    z_prep<<<512, 256>>>(z);

    float* idxf = nullptr;
    if (out_size >= 4194307 + NR) idxf = out + 4194307;

    mma_cand<<<128, 256, SM_TOTAL>>>();
    rescue_kernel<<<NR, 64>>>(idxf);
    gather_out<<<512, 256>>>(z, out);
    finalize_kernel<<<1, 512>>>(out, (out_size >= 4194307) ? 1 : 0);
}

// round 9
// speedup vs baseline: 1.6314x; 1.6314x over previous
#include <cuda_runtime.h>
#include <cuda_fp16.h>
#include <cstdint>

// Problem constants
#define KC  8192          // number of codes
#define DD  256           // embedding / channel dim
#define NR  16384         // B*H*W rows
#define HW  1024          // H*W
#define CHW (DD * HW)     // per-batch stride in z / out

#define CAPM    24        // candidate list capacity per row
#define MARGIN  4e-4f     // >= 8x worst-case fp16 score error (~5e-5)

// Scratch (static device memory)
__device__ float g_codebook[KC * DD];        // emb @ proj_w^T fp32
__device__ float g_zf[NR * DD];              // z transposed [N][D] fp32
__device__ float g_zn[NR];                   // ||z_n||^2 (fp32 chain)
__device__ int   g_cand[NR * CAPM];          // candidate indices
__device__ int   g_cand_cnt[NR];             // count (>CAPM = overflow)
__device__ int   g_minidx[NR];
__device__ float g_partials[512];

// half2 operands, d-pair-major: [dp 0..127][index]
__device__ __align__(16) __half2 g_cbh2[128 * KC];   // codebook^T pairs
__device__ __align__(16) __half2 g_zh2[128 * NR];    // z pairs

// ---------------- helpers ----------------
__device__ __forceinline__ uint32_t smem_u32(const void* p) {
    uint32_t a;
    asm("{ .reg .u64 t; cvta.to.shared.u64 t, %1; cvt.u32.u64 %0, t; }"
        : "=r"(a) : "l"(p));
    return a;
}
__device__ __forceinline__ void cp_async16(uint32_t saddr, const void* g) {
    asm volatile("cp.async.cg.shared.global [%0], [%1], 16;"
                 :: "r"(saddr), "l"(g) : "memory");
}
#define CP_COMMIT() asm volatile("cp.async.commit_group;" ::: "memory")
#define CP_WAIT0()  asm volatile("cp.async.wait_group 0;" ::: "memory")

// ---------------------------------------------------------------------------
// Kernel 1: codebook = emb @ proj^T (exact fp32 sequential-j chain) +
// fused half2 transposed pack into g_cbh2[dp][k].
// ---------------------------------------------------------------------------
__global__ void codebook_gemm(const float* __restrict__ emb,
                              const float* __restrict__ pw) {
    __shared__ float As[16 * 65];
    __shared__ float Bs[16 * 65];
    const int tid = threadIdx.x;
    const int tx = tid & 15, ty = tid >> 4;
    const int k0 = blockIdx.y * 64;
    const int d0 = blockIdx.x * 64;
    const int rl = tid >> 2;
    const int j4 = (tid & 3) << 2;

    float acc[4][4];
#pragma unroll
    for (int u = 0; u < 4; u++)
#pragma unroll
        for (int v = 0; v < 4; v++) acc[u][v] = 0.f;

    for (int j0 = 0; j0 < DD; j0 += 16) {
        float4 va = *(const float4*)&emb[(k0 + rl) * DD + j0 + j4];
        float4 vb = *(const float4*)&pw[(d0 + rl) * DD + j0 + j4];
        As[(j4 + 0) * 65 + rl] = va.x;  As[(j4 + 1) * 65 + rl] = va.y;
        As[(j4 + 2) * 65 + rl] = va.z;  As[(j4 + 3) * 65 + rl] = va.w;
        Bs[(j4 + 0) * 65 + rl] = vb.x;  Bs[(j4 + 1) * 65 + rl] = vb.y;
        Bs[(j4 + 2) * 65 + rl] = vb.z;  Bs[(j4 + 3) * 65 + rl] = vb.w;
        __syncthreads();
#pragma unroll
        for (int jj = 0; jj < 16; jj++) {
            const float* ap = &As[jj * 65 + ty * 4];
            const float* bp = &Bs[jj * 65 + tx * 4];
            float a0 = ap[0], a1 = ap[1], a2 = ap[2], a3 = ap[3];
            float b0 = bp[0], b1 = bp[1], b2 = bp[2], b3 = bp[3];
            acc[0][0] = fmaf(a0, b0, acc[0][0]); acc[0][1] = fmaf(a0, b1, acc[0][1]);
            acc[0][2] = fmaf(a0, b2, acc[0][2]); acc[0][3] = fmaf(a0, b3, acc[0][3]);
            acc[1][0] = fmaf(a1, b0, acc[1][0]); acc[1][1] = fmaf(a1, b1, acc[1][1]);
            acc[1][2] = fmaf(a1, b2, acc[1][2]); acc[1][3] = fmaf(a1, b3, acc[1][3]);
            acc[2][0] = fmaf(a2, b0, acc[2][0]); acc[2][1] = fmaf(a2, b1, acc[2][1]);
            acc[2][2] = fmaf(a2, b2, acc[2][2]); acc[2][3] = fmaf(a2, b3, acc[2][3]);
            acc[3][0] = fmaf(a3, b0, acc[3][0]); acc[3][1] = fmaf(a3, b1, acc[3][1]);
            acc[3][2] = fmaf(a3, b2, acc[3][2]); acc[3][3] = fmaf(a3, b3, acc[3][3]);
        }
        __syncthreads();
    }
#pragma unroll
    for (int u = 0; u < 4; u++) {
        int k = k0 + ty * 4 + u;
        float4 w = make_float4(acc[u][0], acc[u][1], acc[u][2], acc[u][3]);
        *(float4*)&g_codebook[k * DD + d0 + tx * 4] = w;
        int dp0 = (d0 + tx * 4) >> 1;
        g_cbh2[(dp0 + 0) * KC + k] = __floats2half2_rn(acc[u][0], acc[u][1]);
        g_cbh2[(dp0 + 1) * KC + k] = __floats2half2_rn(acc[u][2], acc[u][3]);
    }
}

// ---------------------------------------------------------------------------
// Kernel 2: z transpose -> g_zf [N][D] fp32, zn per row (sequential chain),
// fused half2 pair pack into g_zh2[dp][n].
// ---------------------------------------------------------------------------
__global__ void z_prep(const float* __restrict__ z) {
    __shared__ float Zs[256 * 33];
    const int tid = threadIdx.x;
    const int n0 = blockIdx.x * 32;
    const int b = n0 >> 10, hw0 = n0 & 1023;
    const float* zb = z + b * CHW + hw0;

    for (int e = tid; e < 32 * DD; e += 256) {
        int d = e >> 5, m = e & 31;
        Zs[d * 33 + m] = zb[d * HW + m];
    }
    __syncthreads();
    // fp32 transposed copy for rescue
    for (int idx = tid; idx < 32 * DD; idx += 256) {
        int nl = idx >> 8, d = idx & 255;
        g_zf[(n0 + nl) * DD + d] = Zs[d * 33 + nl];
    }
    // half2 pair pack (nl fastest -> coalesced 4B stores)
    for (int idx = tid; idx < 32 * 128; idx += 256) {
        int nl = idx & 31, dp = idx >> 5;
        g_zh2[dp * NR + n0 + nl] =
            __floats2half2_rn(Zs[(2 * dp) * 33 + nl], Zs[(2 * dp + 1) * 33 + nl]);
    }
    if (tid < 32) {
        float s = 0.f;
#pragma unroll 8
        for (int d = 0; d < DD; d++) { float v = Zs[d * 33 + tid]; s = fmaf(v, v, s); }
        g_zn[n0 + tid] = s;
    }
}

// ---------------------------------------------------------------------------
// Kernel 3: HFMA2 distance GEMM + margin candidate collect.
// Block = 64 rows resident (Zh [dp][row] half2, 32KB); streams codebook in
// 128 chunks of 64 codes (Es [dp][code] half2, double-buffered cp.async).
// Thread tile 4 rows x 4 codes: per dp, 2x LDS.128 + 16 HFMA2.
// half2 accumulators merged to fp32 every 32 d-pairs (error << MARGIN).
// ---------------------------------------------------------------------------
#define ZH_OFF    0
#define ES_OFF    32768
#define LIST_OFF  98304
#define CNT_OFF   (LIST_OFF + 64 * CAPM * 4)
#define SMEM_H2   (CNT_OFF + 64 * 4)

__global__ __launch_bounds__(256, 2)
void argmin_h2(float* __restrict__ idxf) {
    extern __shared__ char sm[];
    const uint32_t sbase = smem_u32(sm);
    __half2* Zh = (__half2*)(sm + ZH_OFF);     // [128][64]
    int* slist  = (int*)(sm + LIST_OFF);
    int* scnt   = (int*)(sm + CNT_OFF);

    const int tid = threadIdx.x;
    const int tx = tid & 15, ty = tid >> 4;
    const int n0 = blockIdx.x * 64;

    if (tid < 64) scnt[tid] = 0;

    // Load resident z tile: Zh[dp][r] from g_zh2[dp*NR + n0 + r]
    for (int i = tid; i < 2048; i += 256) {
        int dp = i >> 4, seg = i & 15;
        *(uint4*)&Zh[dp * 64 + seg * 4] =
            *(const uint4*)&g_zh2[dp * NR + n0 + seg * 4];
    }
    // Preload Es chunk 0
    for (int i = tid; i < 2048; i += 256) {
        int dp = i >> 4, seg = i & 15;
        cp_async16(sbase + ES_OFF + (dp * 64 + seg * 4) * 4,
                   g_cbh2 + dp * KC + seg * 4);
    }
    CP_COMMIT();
    CP_WAIT0();
    __syncthreads();

    float zn[4], rm[4];
#pragma unroll
    for (int r = 0; r < 4; r++) {
        zn[r] = g_zn[n0 + ty * 4 + r];
        rm[r] = 3.4e38f;
    }

    for (int c = 0; c < 128; c++) {
        if (c + 1 < 128) {
            int kn = (c + 1) * 64;
            uint32_t dst = sbase + ES_OFF + ((c + 1) & 1) * 32768;
            for (int i = tid; i < 2048; i += 256) {
                int dp = i >> 4, seg = i & 15;
                cp_async16(dst + (dp * 64 + seg * 4) * 4,
                           g_cbh2 + dp * KC + kn + seg * 4);
            }
            CP_COMMIT();
        }

        const __half2* Zp = Zh + ty * 4;
        const __half2* Ep = (const __half2*)(sm + ES_OFF + (c & 1) * 32768) + tx * 4;

        float c32[4][4];
#pragma unroll
        for (int r = 0; r < 4; r++)
#pragma unroll
            for (int v = 0; v < 4; v++) c32[r][v] = 0.f;

#pragma unroll 1
        for (int o = 0; o < 4; o++) {           // 4 blocks of 32 d-pairs
            __half2 h[4][4];
            const __half2 hz = __floats2half2_rn(0.f, 0.f);
#pragma unroll
            for (int r = 0; r < 4; r++)
#pragma unroll
                for (int v = 0; v < 4; v++) h[r][v] = hz;
#pragma unroll
            for (int d = 0; d < 32; d++) {
                int dp = o * 32 + d;
                float4 zv = *(const float4*)(Zp + dp * 64);
                float4 ev = *(const float4*)(Ep + dp * 64);
                __half2 z0 = *(__half2*)&zv.x, z1 = *(__half2*)&zv.y;
                __half2 z2 = *(__half2*)&zv.z, z3 = *(__half2*)&zv.w;
                __half2 e0 = *(__half2*)&ev.x, e1 = *(__half2*)&ev.y;
                __half2 e2 = *(__half2*)&ev.z, e3 = *(__half2*)&ev.w;
                h[0][0] = __hfma2(z0, e0, h[0][0]); h[0][1] = __hfma2(z0, e1, h[0][1]);
                h[0][2] = __hfma2(z0, e2, h[0][2]); h[0][3] = __hfma2(z0, e3, h[0][3]);
                h[1][0] = __hfma2(z1, e0, h[1][0]); h[1][1] = __hfma2(z1, e1, h[1][1]);
                h[1][2] = __hfma2(z1, e2, h[1][2]); h[1][3] = __hfma2(z1, e3, h[1][3]);
                h[2][0] = __hfma2(z2, e0, h[2][0]); h[2][1] = __hfma2(z2, e1, h[2][1]);
                h[2][2] = __hfma2(z2, e2, h[2][2]); h[2][3] = __hfma2(z2, e3, h[2][3]);
                h[3][0] = __hfma2(z3, e0, h[3][0]); h[3][1] = __hfma2(z3, e1, h[3][1]);
                h[3][2] = __hfma2(z3, e2, h[3][2]); h[3][3] = __hfma2(z3, e3, h[3][3]);
            }
            // fp32 merge
#pragma unroll
            for (int r = 0; r < 4; r++)
#pragma unroll
                for (int v = 0; v < 4; v++)
                    c32[r][v] += __low2float(h[r][v]) + __high2float(h[r][v]);
        }

        // epilogue: approx score + margin candidate collection
        const int kc0 = c * 64 + tx * 4;
#pragma unroll
        for (int r = 0; r < 4; r++) {
            const int row = ty * 4 + r;
            const float znr = zn[r];
#pragma unroll
            for (int v = 0; v < 4; v++) {
                float s = fmaf(-2.f, c32[r][v], znr);
                if (s < rm[r] + MARGIN) {
                    if (s < rm[r]) rm[r] = s;
                    int sl = atomicAdd(&scnt[row], 1);
                    if (sl < CAPM) slist[row * CAPM + sl] = kc0 + v;
                }
            }
        }

        if (c + 1 < 128) CP_WAIT0();
        __syncthreads();
    }

    if (tid < 64) {
        int cnt = scnt[tid];
        int n = n0 + tid;
        g_cand_cnt[n] = (cnt > CAPM) ? (CAPM + 1) : cnt;
        int m = (cnt < CAPM) ? cnt : CAPM;
        for (int j = 0; j < m; j++) g_cand[n * CAPM + j] = slist[tid * CAPM + j];
    }
}

// ---------------------------------------------------------------------------
// Kernel 4: exact rescue (bit-exact sequential fp32 chain over candidates).
// Validated bit-exact in Round 7 (rel_err 0.0).
// ---------------------------------------------------------------------------
__global__ __launch_bounds__(64)
void rescue_kernel(float* __restrict__ idxf) {
    __shared__ float zrow[DD];
    __shared__ float rv[64];
    __shared__ int   ri[64];
    const int n = blockIdx.x;
    const int tid = threadIdx.x;

    *(float4*)&zrow[tid * 4] = *(const float4*)&g_zf[n * DD + tid * 4];
    __syncthreads();
    const float zn = g_zn[n];

    float bv = 3.4e38f; int bi = 0x7FFFFFFF;
    int cnt = g_cand_cnt[n];
    if (cnt > CAPM) {
        for (int k = tid; k < KC; k += 64) {
            float acc = 0.f;
            const float4* cb = (const float4*)&g_codebook[k * DD];
#pragma unroll 4
            for (int d4 = 0; d4 < 64; d4++) {
                float4 cc = cb[d4];
                float4 zv = *(const float4*)&zrow[d4 * 4];
                acc = fmaf(zv.x, cc.x, acc); acc = fmaf(zv.y, cc.y, acc);
                acc = fmaf(zv.z, cc.z, acc); acc = fmaf(zv.w, cc.w, acc);
            }
            float s = fmaf(-2.f, acc, zn);
            if (s < bv || (s == bv && k < bi)) { bv = s; bi = k; }
        }
    } else {
        for (int j = tid; j < cnt; j += 64) {
            int k = g_cand[n * CAPM + j];
            float acc = 0.f;
            const float4* cb = (const float4*)&g_codebook[k * DD];
#pragma unroll 4
            for (int d4 = 0; d4 < 64; d4++) {
                float4 cc = cb[d4];
                float4 zv = *(const float4*)&zrow[d4 * 4];
                acc = fmaf(zv.x, cc.x, acc); acc = fmaf(zv.y, cc.y, acc);
                acc = fmaf(zv.z, cc.z, acc); acc = fmaf(zv.w, cc.w, acc);
            }
            float s = fmaf(-2.f, acc, zn);
            if (s < bv || (s == bv && k < bi)) { bv = s; bi = k; }
        }
    }
    rv[tid] = bv; ri[tid] = bi;
    __syncthreads();
    for (int o = 32; o; o >>= 1) {
        if (tid < o) {
            float v = rv[tid + o]; int i2 = ri[tid + o];
            if (v < rv[tid] || (v == rv[tid] && i2 < ri[tid])) {
                rv[tid] = v; ri[tid] = i2;
            }
        }
        __syncthreads();
    }
    if (tid == 0) {
        g_minidx[n] = ri[0];
        if (idxf) idxf[n] = (float)ri[0];
    }
}

// ---------------------------------------------------------------------------
// Kernel 5: gather + straight-through output + squared error partials.
// out = fl(zt + fl(zq - zt)) exactly as the reference.
// ---------------------------------------------------------------------------
__global__ void gather_out(const float* __restrict__ z, float* __restrict__ out) {
    __shared__ float s[256 * 33];
    const int tid = threadIdx.x;
    const int n0 = blockIdx.x * 32;
    const int b = n0 >> 10, hw0 = n0 & 1023;

#pragma unroll 1
    for (int nl = 0; nl < 32; nl++) {
        int ci = g_minidx[n0 + nl];
        s[tid * 33 + nl] = g_codebook[ci * DD + tid];
    }
    __syncthreads();

    float local = 0.f;
    const float* zb = z + b * CHW + hw0;
    float* ob = out + b * CHW + hw0;
    for (int e = tid; e < 32 * DD; e += 256) {
        int c = e >> 5, hl = e & 31;
        float q  = s[c * 33 + hl];
        float zv = zb[c * HW + hl];
        float d  = q - zv;
        ob[c * HW + hl] = zv + d;
        local = fmaf(d, d, local);
    }
    __syncthreads();
    float* red = s;
    red[tid] = local;
    __syncthreads();
    for (int o = 128; o; o >>= 1) {
        if (tid < o) red[tid] += red[tid + o];
        __syncthreads();
    }
    if (tid == 0) g_partials[blockIdx.x] = red[0];
}

// ---------------------------------------------------------------------------
// Kernel 6: final reduction + loss scalars
// ---------------------------------------------------------------------------
__global__ void finalize_kernel(float* __restrict__ outp, int has_scalars) {
    __shared__ float red[512];
    const int tid = threadIdx.x;
    red[tid] = g_partials[tid];
    __syncthreads();
    for (int o = 256; o; o >>= 1) {
        if (tid < o) red[tid] += red[tid + o];
        __syncthreads();
    }
    if (tid == 0 && has_scalars) {
        float mse = red[0] * (1.0f / 4194304.0f);
        float cl  = 0.25f * mse;
        float bl  = mse;
        outp[4194304] = cl + bl;
        outp[4194305] = cl;
        outp[4194306] = bl;
    }
}

// ---------------------------------------------------------------------------
extern "C" void kernel_launch(void* const* d_in, const int* in_sizes, int n_in,
                              void* d_out, int out_size) {
    const float* z   = (const float*)d_in[0];   // [16,256,32,32]
    const float* emb = (const float*)d_in[1];   // [8192,256]
    const float* pw  = (const float*)d_in[2];   // [256,256]
    float* out = (float*)d_out;

    cudaFuncSetAttribute(argmin_h2,
                         cudaFuncAttributeMaxDynamicSharedMemorySize, SMEM_H2);

    codebook_gemm<<<dim3(4, 128), 256>>>(emb, pw);
    z_prep<<<512, 256>>>(z);

    float* idxf = nullptr;
    if (out_size >= 4194307 + NR) idxf = out + 4194307;

    argmin_h2<<<256, 256, SMEM_H2>>>(idxf);
    rescue_kernel<<<NR, 64>>>(idxf);
    gather_out<<<512, 256>>>(z, out);
    finalize_kernel<<<1, 512>>>(out, (out_size >= 4194307) ? 1 : 0);
}

// round 11
// speedup vs baseline: 1.6519x; 1.0126x over previous
#include <cuda_runtime.h>
#include <cstdint>

// Problem constants
#define KC  8192          // number of codes
#define DD  256           // embedding / channel dim
#define NR  16384         // B*H*W rows
#define HW  1024          // H*W
#define CHW (DD * HW)     // per-batch stride in z / out

#define CAPM    24        // candidate list capacity per row
#define MARGIN  8e-4f     // ~17 sigma of int8 score error

// int8 quantization scales
#define SZF  22.0f        // z scale: covers |z| <= 5.77 (5.8 sigma)
#define SEF  260000.0f    // codebook scale: covers |e| <= 4.88e-4 (6.9 sigma)
#define M2INV (-2.0f / (SZF * SEF))

// Scratch (static device memory)
__device__ float g_codebook[KC * DD];        // emb @ proj_w^T fp32
__device__ float g_zf[NR * DD];              // z transposed [N][D] fp32
__device__ float g_zn[NR];                   // ||z_n||^2 (fp32 chain)
__device__ int   g_cand[NR * CAPM];          // candidate indices
__device__ int   g_cand_cnt[NR];             // count (>CAPM = overflow)
__device__ int   g_minidx[NR];
__device__ float g_partials[512];

// int8-packed operands, d-quad-major (dq = d/4), 4 bytes = 4 consecutive d
__device__ __align__(16) int g_zq[64 * NR];  // [dq][n]
__device__ __align__(16) int g_cq[64 * KC];  // [dq][k]

// ---------------- helpers ----------------
__device__ __forceinline__ int q8(float v, float s) {
    int x = __float2int_rn(v * s);
    return max(-127, min(127, x));
}
__device__ __forceinline__ int pack4(int b0, int b1, int b2, int b3) {
    return (b0 & 0xFF) | ((b1 & 0xFF) << 8) | ((b2 & 0xFF) << 16) | (b3 << 24);
}

// ---------------------------------------------------------------------------
// Kernel 1: codebook = emb @ proj^T (exact fp32 sequential-j chain) +
// fused int8 quantized transposed pack into g_cq[dq][k].
// ---------------------------------------------------------------------------
__global__ void codebook_gemm(const float* __restrict__ emb,
                              const float* __restrict__ pw) {
    __shared__ float As[16 * 65];
    __shared__ float Bs[16 * 65];
    const int tid = threadIdx.x;
    const int tx = tid & 15, ty = tid >> 4;
    const int k0 = blockIdx.y * 64;
    const int d0 = blockIdx.x * 64;
    const int rl = tid >> 2;
    const int j4 = (tid & 3) << 2;

    float acc[4][4];
#pragma unroll
    for (int u = 0; u < 4; u++)
#pragma unroll
        for (int v = 0; v < 4; v++) acc[u][v] = 0.f;

    for (int j0 = 0; j0 < DD; j0 += 16) {
        float4 va = *(const float4*)&emb[(k0 + rl) * DD + j0 + j4];
        float4 vb = *(const float4*)&pw[(d0 + rl) * DD + j0 + j4];
        As[(j4 + 0) * 65 + rl] = va.x;  As[(j4 + 1) * 65 + rl] = va.y;
        As[(j4 + 2) * 65 + rl] = va.z;  As[(j4 + 3) * 65 + rl] = va.w;
        Bs[(j4 + 0) * 65 + rl] = vb.x;  Bs[(j4 + 1) * 65 + rl] = vb.y;
        Bs[(j4 + 2) * 65 + rl] = vb.z;  Bs[(j4 + 3) * 65 + rl] = vb.w;
        __syncthreads();
#pragma unroll
        for (int jj = 0; jj < 16; jj++) {
            const float* ap = &As[jj * 65 + ty * 4];
            const float* bp = &Bs[jj * 65 + tx * 4];
            float a0 = ap[0], a1 = ap[1], a2 = ap[2], a3 = ap[3];
            float b0 = bp[0], b1 = bp[1], b2 = bp[2], b3 = bp[3];
            acc[0][0] = fmaf(a0, b0, acc[0][0]); acc[0][1] = fmaf(a0, b1, acc[0][1]);
            acc[0][2] = fmaf(a0, b2, acc[0][2]); acc[0][3] = fmaf(a0, b3, acc[0][3]);
            acc[1][0] = fmaf(a1, b0, acc[1][0]); acc[1][1] = fmaf(a1, b1, acc[1][1]);
            acc[1][2] = fmaf(a1, b2, acc[1][2]); acc[1][3] = fmaf(a1, b3, acc[1][3]);
            acc[2][0] = fmaf(a2, b0, acc[2][0]); acc[2][1] = fmaf(a2, b1, acc[2][1]);
            acc[2][2] = fmaf(a2, b2, acc[2][2]); acc[2][3] = fmaf(a2, b3, acc[2][3]);
            acc[3][0] = fmaf(a3, b0, acc[3][0]); acc[3][1] = fmaf(a3, b1, acc[3][1]);
            acc[3][2] = fmaf(a3, b2, acc[3][2]); acc[3][3] = fmaf(a3, b3, acc[3][3]);
        }
        __syncthreads();
    }
    const int dq = (d0 >> 2) + tx;   // one d-quad per tx
#pragma unroll
    for (int u = 0; u < 4; u++) {
        int k = k0 + ty * 4 + u;
        float4 w = make_float4(acc[u][0], acc[u][1], acc[u][2], acc[u][3]);
        *(float4*)&g_codebook[k * DD + d0 + tx * 4] = w;
        g_cq[dq * KC + k] = pack4(q8(acc[u][0], SEF), q8(acc[u][1], SEF),
                                  q8(acc[u][2], SEF), q8(acc[u][3], SEF));
    }
}

// ---------------------------------------------------------------------------
// Kernel 2: z transpose -> g_zf [N][D] fp32, zn per row (sequential chain),
// fused int8 pack into g_zq[dq][n].
// ---------------------------------------------------------------------------
__global__ void z_prep(const float* __restrict__ z) {
    __shared__ float Zs[256 * 33];
    const int tid = threadIdx.x;
    const int n0 = blockIdx.x * 32;
    const int b = n0 >> 10, hw0 = n0 & 1023;
    const float* zb = z + b * CHW + hw0;

    for (int e = tid; e < 32 * DD; e += 256) {
        int d = e >> 5, m = e & 31;
        Zs[d * 33 + m] = zb[d * HW + m];
    }
    __syncthreads();
    // fp32 transposed copy for rescue
    for (int idx = tid; idx < 32 * DD; idx += 256) {
        int nl = idx >> 8, d = idx & 255;
        g_zf[(n0 + nl) * DD + d] = Zs[d * 33 + nl];
    }
    // int8 quad pack (nl fastest -> coalesced 4B stores)
    for (int idx = tid; idx < 32 * 64; idx += 256) {
        int nl = idx & 31, dq = idx >> 5;
        g_zq[dq * NR + n0 + nl] =
            pack4(q8(Zs[(4 * dq + 0) * 33 + nl], SZF),
                  q8(Zs[(4 * dq + 1) * 33 + nl], SZF),
                  q8(Zs[(4 * dq + 2) * 33 + nl], SZF),
                  q8(Zs[(4 * dq + 3) * 33 + nl], SZF));
    }
    if (tid < 32) {
        float s = 0.f;
#pragma unroll 8
        for (int d = 0; d < DD; d++) { float v = Zs[d * 33 + tid]; s = fmaf(v, v, s); }
        g_zn[n0 + tid] = s;
    }
}

// ---------------------------------------------------------------------------
// Kernel 3: dp4a int8 distance GEMM + margin candidate collect.
// Block = 64 rows resident (Zs [dq][row] int32, 16KB); streams codebook in
// 64 chunks of 128 codes (Es [dq][code] int32, register-prefetch LDG->STS,
// NO cp.async). Thread tile 8 rows x 4 codes: per dq, 3x LDS.128 + 32 dp4a.
// int32 accumulation exact; approx score s = fmaf(acc, M2INV, zn).
// ---------------------------------------------------------------------------
#define ZS_OFF    0
#define ES_OFF    16384
#define LIST_OFF  49152
#define CNT_OFF   (LIST_OFF + 64 * CAPM * 4)
#define SMEM_DP4A (CNT_OFF + 64 * 4)

__global__ __launch_bounds__(256, 2)
void argmin_dp4a(void) {
    extern __shared__ char sm[];
    int* Zs     = (int*)(sm + ZS_OFF);     // [64 dq][64 rows]
    int* Es     = (int*)(sm + ES_OFF);     // [64 dq][128 codes]
    int* slist  = (int*)(sm + LIST_OFF);
    int* scnt   = (int*)(sm + CNT_OFF);

    const int tid = threadIdx.x;
    const int rg = (tid >> 5) * 8;         // my 8 rows
    const int cg = (tid & 31) * 4;         // my 4 codes within chunk
    const int n0 = blockIdx.x * 64;

    if (tid < 64) scnt[tid] = 0;

    // Load resident z tile: Zs[dq][r]
    for (int i = tid; i < 1024; i += 256) {
        int dq = i >> 4, seg = i & 15;
        *(uint4*)&Zs[dq * 64 + seg * 4] =
            *(const uint4*)&g_zq[dq * NR + n0 + seg * 4];
    }
    // Prefetch codebook chunk 0 into registers (8 x 16B per thread = 32KB/CTA)
    uint4 pre[8];
#pragma unroll
    for (int j = 0; j < 8; j++) {
        int idx = tid * 8 + j;
        int dq = idx >> 5, cs = idx & 31;
        pre[j] = *(const uint4*)&g_cq[dq * KC + cs * 4];
    }

    float zn[8], rm[8];
#pragma unroll
    for (int r = 0; r < 8; r++) {
        zn[r] = g_zn[n0 + rg + r];
        rm[r] = 3.4e38f;
    }

    for (int it = 0; it < 64; it++) {
        // store prefetched chunk
#pragma unroll
        for (int j = 0; j < 8; j++) {
            int idx = tid * 8 + j;
            int dq = idx >> 5, cs = idx & 31;
            *(uint4*)&Es[dq * 128 + cs * 4] = pre[j];
        }
        __syncthreads();

        // prefetch next chunk while computing
        if (it + 1 < 64) {
            const int kn = (it + 1) * 128;
#pragma unroll
            for (int j = 0; j < 8; j++) {
                int idx = tid * 8 + j;
                int dq = idx >> 5, cs = idx & 15 * 2 + (idx & 31) - (idx & 31) + (idx & 31); // see below
            }
        }
        // (clean prefetch loop — the above placeholder removed)
        uint4 nxt[8];
        if (it + 1 < 64) {
            const int kn = (it + 1) * 128;
#pragma unroll
            for (int j = 0; j < 8; j++) {
                int idx = tid * 8 + j;
                int dq = idx >> 5, cs = idx & 31;
                nxt[j] = *(const uint4*)&g_cq[dq * KC + kn + cs * 4];
            }
        }

        int acc[8][4];
#pragma unroll
        for (int r = 0; r < 8; r++)
#pragma unroll
            for (int v = 0; v < 4; v++) acc[r][v] = 0;

#pragma unroll 4
        for (int dq = 0; dq < 64; dq++) {
            uint4 z0 = *(const uint4*)&Zs[dq * 64 + rg];       // rows rg..rg+3
            uint4 z1 = *(const uint4*)&Zs[dq * 64 + rg + 4];   // rows rg+4..+7
            uint4 ev = *(const uint4*)&Es[dq * 128 + cg];      // codes cg..cg+3
            const int zw[8] = {(int)z0.x, (int)z0.y, (int)z0.z, (int)z0.w,
                               (int)z1.x, (int)z1.y, (int)z1.z, (int)z1.w};
            const int ew[4] = {(int)ev.x, (int)ev.y, (int)ev.z, (int)ev.w};
#pragma unroll
            for (int r = 0; r < 8; r++) {
                acc[r][0] = __dp4a(zw[r], ew[0], acc[r][0]);
                acc[r][1] = __dp4a(zw[r], ew[1], acc[r][1]);
                acc[r][2] = __dp4a(zw[r], ew[2], acc[r][2]);
                acc[r][3] = __dp4a(zw[r], ew[3], acc[r][3]);
            }
        }

        // epilogue: approx score + margin candidate collection
        const int kb = it * 128 + cg;
#pragma unroll
        for (int r = 0; r < 8; r++) {
            const int row = rg + r;
            const float znr = zn[r];
#pragma unroll
            for (int v = 0; v < 4; v++) {
                float s = fmaf((float)acc[r][v], M2INV, znr);
                if (s < rm[r] + MARGIN) {
                    if (s < rm[r]) rm[r] = s;
                    int sl = atomicAdd(&scnt[row], 1);
                    if (sl < CAPM) slist[row * CAPM + sl] = kb + v;
                }
            }
        }

#pragma unroll
        for (int j = 0; j < 8; j++) pre[j] = nxt[j];
        __syncthreads();
    }

    if (tid < 64) {
        int cnt = scnt[tid];
        int n = n0 + tid;
        g_cand_cnt[n] = (cnt > CAPM) ? (CAPM + 1) : cnt;
        int m = (cnt < CAPM) ? cnt : CAPM;
        for (int j = 0; j < m; j++) g_cand[n * CAPM + j] = slist[tid * CAPM + j];
    }
}

// ---------------------------------------------------------------------------
// Kernel 4: exact rescue (bit-exact sequential fp32 chain over candidates).
// Validated bit-exact in Rounds 7/9 (rel_err 0.0).
// ---------------------------------------------------------------------------
__global__ __launch_bounds__(64)
void rescue_kernel(float* __restrict__ idxf) {
    __shared__ float zrow[DD];
    __shared__ float rv[64];
    __shared__ int   ri[64];
    const int n = blockIdx.x;
    const int tid = threadIdx.x;

    *(float4*)&zrow[tid * 4] = *(const float4*)&g_zf[n * DD + tid * 4];
    __syncthreads();
    const float zn = g_zn[n];

    float bv = 3.4e38f; int bi = 0x7FFFFFFF;
    int cnt = g_cand_cnt[n];
    if (cnt > CAPM) {
        for (int k = tid; k < KC; k += 64) {
            float acc = 0.f;
            const float4* cb = (const float4*)&g_codebook[k * DD];
#pragma unroll 4
            for (int d4 = 0; d4 < 64; d4++) {
                float4 cc = cb[d4];
                float4 zv = *(const float4*)&zrow[d4 * 4];
                acc = fmaf(zv.x, cc.x, acc); acc = fmaf(zv.y, cc.y, acc);
                acc = fmaf(zv.z, cc.z, acc); acc = fmaf(zv.w, cc.w, acc);
            }
            float s = fmaf(-2.f, acc, zn);
            if (s < bv || (s == bv && k < bi)) { bv = s; bi = k; }
        }
    } else {
        for (int j = tid; j < cnt; j += 64) {
            int k = g_cand[n * CAPM + j];
            float acc = 0.f;
            const float4* cb = (const float4*)&g_codebook[k * DD];
#pragma unroll 4
            for (int d4 = 0; d4 < 64; d4++) {
                float4 cc = cb[d4];
                float4 zv = *(const float4*)&zrow[d4 * 4];
                acc = fmaf(zv.x, cc.x, acc); acc = fmaf(zv.y, cc.y, acc);
                acc = fmaf(zv.z, cc.z, acc); acc = fmaf(zv.w, cc.w, acc);
            }
            float s = fmaf(-2.f, acc, zn);
            if (s < bv || (s == bv && k < bi)) { bv = s; bi = k; }
        }
    }
    rv[tid] = bv; ri[tid] = bi;
    __syncthreads();
    for (int o = 32; o; o >>= 1) {
        if (tid < o) {
            float v = rv[tid + o]; int i2 = ri[tid + o];
            if (v < rv[tid] || (v == rv[tid] && i2 < ri[tid])) {
                rv[tid] = v; ri[tid] = i2;
            }
        }
        __syncthreads();
    }
    if (tid == 0) {
        g_minidx[n] = ri[0];
        if (idxf) idxf[n] = (float)ri[0];
    }
}

// ---------------------------------------------------------------------------
// Kernel 5: gather + straight-through output + squared error partials.
// out = fl(zt + fl(zq - zt)) exactly as the reference.
// ---------------------------------------------------------------------------
__global__ void gather_out(const float* __restrict__ z, float* __restrict__ out) {
    __shared__ float s[256 * 33];
    const int tid = threadIdx.x;
    const int n0 = blockIdx.x * 32;
    const int b = n0 >> 10, hw0 = n0 & 1023;

#pragma unroll 1
    for (int nl = 0; nl < 32; nl++) {
        int ci = g_minidx[n0 + nl];
        s[tid * 33 + nl] = g_codebook[ci * DD + tid];
    }
    __syncthreads();

    float local = 0.f;
    const float* zb = z + b * CHW + hw0;
    float* ob = out + b * CHW + hw0;
    for (int e = tid; e < 32 * DD; e += 256) {
        int c = e >> 5, hl = e & 31;
        float q  = s[c * 33 + hl];
        float zv = zb[c * HW + hl];
        float d  = q - zv;
        ob[c * HW + hl] = zv + d;
        local = fmaf(d, d, local);
    }
    __syncthreads();
    float* red = s;
    red[tid] = local;
    __syncthreads();
    for (int o = 128; o; o >>= 1) {
        if (tid < o) red[tid] += red[tid + o];
        __syncthreads();
    }
    if (tid == 0) g_partials[blockIdx.x] = red[0];
}

// ---------------------------------------------------------------------------
// Kernel 6: final reduction + loss scalars
// ---------------------------------------------------------------------------
__global__ void finalize_kernel(float* __restrict__ outp, int has_scalars) {
    __shared__ float red[512];
    const int tid = threadIdx.x;
    red[tid] = g_partials[tid];
    __syncthreads();
    for (int o = 256; o; o >>= 1) {
        if (tid < o) red[tid] += red[tid + o];
        __syncthreads();
    }
    if (tid == 0 && has_scalars) {
        float mse = red[0] * (1.0f / 4194304.0f);
        float cl  = 0.25f * mse;
        float bl  = mse;
        outp[4194304] = cl + bl;
        outp[4194305] = cl;
        outp[4194306] = bl;
    }
}

// ---------------------------------------------------------------------------
extern "C" void kernel_launch(void* const* d_in, const int* in_sizes, int n_in,
                              void* d_out, int out_size) {
    const float* z   = (const float*)d_in[0];   // [16,256,32,32]
    const float* emb = (const float*)d_in[1];   // [8192,256]
    const float* pw  = (const float*)d_in[2];   // [256,256]
    float* out = (float*)d_out;

    cudaFuncSetAttribute(argmin_dp4a,
                         cudaFuncAttributeMaxDynamicSharedMemorySize, SMEM_DP4A);

    codebook_gemm<<<dim3(4, 128), 256>>>(emb, pw);
    z_prep<<<512, 256>>>(z);

    float* idxf = nullptr;
    if (out_size >= 4194307 + NR) idxf = out + 4194307;

    argmin_dp4a<<<256, 256, SMEM_DP4A>>>();
    rescue_kernel<<<NR, 64>>>(idxf);
    gather_out<<<512, 256>>>(z, out);
    finalize_kernel<<<1, 512>>>(out, (out_size >= 4194307) ? 1 : 0);
}

// round 12
// speedup vs baseline: 11.2836x; 6.8307x over previous
#include <cuda_runtime.h>
#include <cstdint>

// Problem constants
#define KC  8192          // number of codes
#define DD  256           // embedding / channel dim
#define NR  16384         // B*H*W rows
#define HW  1024          // H*W
#define CHW (DD * HW)     // per-batch stride in z / out

#define CAPM    32        // candidate list capacity per row
#define MARGIN  1e-3f     // ~40 sigma of int8 score error; >= 2*eps superset bound

// int8 quantization scales
#define SZF  22.0f        // z scale: covers |z| <= 5.77
#define SEF  260000.0f    // codebook scale: covers |e| <= 4.88e-4
#define M2INV (-2.0f / (SZF * SEF))

// Scratch (static device memory)
__device__ float g_codebook[KC * DD];        // emb @ proj_w^T fp32
__device__ float g_zf[NR * DD];              // z transposed [N][D] fp32
__device__ float g_zn[NR];                   // ||z_n||^2 (fp32 chain)
__device__ int   g_cand[NR * CAPM];          // candidate indices
__device__ int   g_cand_cnt[NR];             // count (>CAPM = overflow)
__device__ int   g_minidx[NR];
__device__ float g_partials[512];

// int8-packed operands, d-quad-major (dq = d/4), 4 bytes = 4 consecutive d
__device__ __align__(16) int g_zq[64 * NR];  // [dq][n]
__device__ __align__(16) int g_cq[64 * KC];  // [dq][k]

// ---------------- helpers ----------------
__device__ __forceinline__ int q8(float v, float s) {
    int x = __float2int_rn(v * s);
    return max(-127, min(127, x));
}
__device__ __forceinline__ int pack4(int b0, int b1, int b2, int b3) {
    return (b0 & 0xFF) | ((b1 & 0xFF) << 8) | ((b2 & 0xFF) << 16) | (b3 << 24);
}

// ---------------------------------------------------------------------------
// Kernel 1: codebook = emb @ proj^T (exact fp32 sequential-j chain) +
// fused int8 quantized transposed pack into g_cq[dq][k].
// ---------------------------------------------------------------------------
__global__ void codebook_gemm(const float* __restrict__ emb,
                              const float* __restrict__ pw) {
    __shared__ float As[16 * 65];
    __shared__ float Bs[16 * 65];
    const int tid = threadIdx.x;
    const int tx = tid & 15, ty = tid >> 4;
    const int k0 = blockIdx.y * 64;
    const int d0 = blockIdx.x * 64;
    const int rl = tid >> 2;
    const int j4 = (tid & 3) << 2;

    float acc[4][4];
#pragma unroll
    for (int u = 0; u < 4; u++)
#pragma unroll
        for (int v = 0; v < 4; v++) acc[u][v] = 0.f;

    for (int j0 = 0; j0 < DD; j0 += 16) {
        float4 va = *(const float4*)&emb[(k0 + rl) * DD + j0 + j4];
        float4 vb = *(const float4*)&pw[(d0 + rl) * DD + j0 + j4];
        As[(j4 + 0) * 65 + rl] = va.x;  As[(j4 + 1) * 65 + rl] = va.y;
        As[(j4 + 2) * 65 + rl] = va.z;  As[(j4 + 3) * 65 + rl] = va.w;
        Bs[(j4 + 0) * 65 + rl] = vb.x;  Bs[(j4 + 1) * 65 + rl] = vb.y;
        Bs[(j4 + 2) * 65 + rl] = vb.z;  Bs[(j4 + 3) * 65 + rl] = vb.w;
        __syncthreads();
#pragma unroll
        for (int jj = 0; jj < 16; jj++) {
            const float* ap = &As[jj * 65 + ty * 4];
            const float* bp = &Bs[jj * 65 + tx * 4];
            float a0 = ap[0], a1 = ap[1], a2 = ap[2], a3 = ap[3];
            float b0 = bp[0], b1 = bp[1], b2 = bp[2], b3 = bp[3];
            acc[0][0] = fmaf(a0, b0, acc[0][0]); acc[0][1] = fmaf(a0, b1, acc[0][1]);
            acc[0][2] = fmaf(a0, b2, acc[0][2]); acc[0][3] = fmaf(a0, b3, acc[0][3]);
            acc[1][0] = fmaf(a1, b0, acc[1][0]); acc[1][1] = fmaf(a1, b1, acc[1][1]);
            acc[1][2] = fmaf(a1, b2, acc[1][2]); acc[1][3] = fmaf(a1, b3, acc[1][3]);
            acc[2][0] = fmaf(a2, b0, acc[2][0]); acc[2][1] = fmaf(a2, b1, acc[2][1]);
            acc[2][2] = fmaf(a2, b2, acc[2][2]); acc[2][3] = fmaf(a2, b3, acc[2][3]);
            acc[3][0] = fmaf(a3, b0, acc[3][0]); acc[3][1] = fmaf(a3, b1, acc[3][1]);
            acc[3][2] = fmaf(a3, b2, acc[3][2]); acc[3][3] = fmaf(a3, b3, acc[3][3]);
        }
        __syncthreads();
    }
    const int dq = (d0 >> 2) + tx;   // one d-quad per tx
#pragma unroll
    for (int u = 0; u < 4; u++) {
        int k = k0 + ty * 4 + u;
        float4 w = make_float4(acc[u][0], acc[u][1], acc[u][2], acc[u][3]);
        *(float4*)&g_codebook[k * DD + d0 + tx * 4] = w;
        g_cq[dq * KC + k] = pack4(q8(acc[u][0], SEF), q8(acc[u][1], SEF),
                                  q8(acc[u][2], SEF), q8(acc[u][3], SEF));
    }
}

// ---------------------------------------------------------------------------
// Kernel 2: z transpose -> g_zf [N][D] fp32, zn per row (sequential chain),
// fused int8 pack into g_zq[dq][n].
// ---------------------------------------------------------------------------
__global__ void z_prep(const float* __restrict__ z) {
    __shared__ float Zs[256 * 33];
    const int tid = threadIdx.x;
    const int n0 = blockIdx.x * 32;
    const int b = n0 >> 10, hw0 = n0 & 1023;
    const float* zb = z + b * CHW + hw0;

    for (int e = tid; e < 32 * DD; e += 256) {
        int d = e >> 5, m = e & 31;
        Zs[d * 33 + m] = zb[d * HW + m];
    }
    __syncthreads();
    // fp32 transposed copy for rescue
    for (int idx = tid; idx < 32 * DD; idx += 256) {
        int nl = idx >> 8, d = idx & 255;
        g_zf[(n0 + nl) * DD + d] = Zs[d * 33 + nl];
    }
    // int8 quad pack (nl fastest -> coalesced 4B stores)
    for (int idx = tid; idx < 32 * 64; idx += 256) {
        int nl = idx & 31, dq = idx >> 5;
        g_zq[dq * NR + n0 + nl] =
            pack4(q8(Zs[(4 * dq + 0) * 33 + nl], SZF),
                  q8(Zs[(4 * dq + 1) * 33 + nl], SZF),
                  q8(Zs[(4 * dq + 2) * 33 + nl], SZF),
                  q8(Zs[(4 * dq + 3) * 33 + nl], SZF));
    }
    if (tid < 32) {
        float s = 0.f;
#pragma unroll 8
        for (int d = 0; d < DD; d++) { float v = Zs[d * 33 + tid]; s = fmaf(v, v, s); }
        g_zn[n0 + tid] = s;
    }
}

// ---------------------------------------------------------------------------
// Kernel 3: dp4a int8 distance GEMM + TIGHT margin candidate collect.
// Block = 64 rows resident; 64 chunks of 128 codes (register-prefetch LDG->
// STS, no cp.async). Thread tile 8 rows x 4 codes.
// Epilogue is two-phase: (A) chunk scores -> warp-wide row min merged into
// rm BEFORE any write (each row owned by exactly one warp); (B) write only
// scores < rm + MARGIN. Prevents chunk-0 flooding -> candidate overflow ->
// the full-scan catastrophe diagnosed in R9/R11.
// ---------------------------------------------------------------------------
#define ZS_OFF    0
#define ES_OFF    16384
#define LIST_OFF  49152
#define CNT_OFF   (LIST_OFF + 64 * CAPM * 4)
#define SMEM_DP4A (CNT_OFF + 64 * 4)

__global__ __launch_bounds__(256, 2)
void argmin_dp4a(void) {
    extern __shared__ char sm[];
    int* Zs     = (int*)(sm + ZS_OFF);     // [64 dq][64 rows]
    int* Es     = (int*)(sm + ES_OFF);     // [64 dq][128 codes]
    int* slist  = (int*)(sm + LIST_OFF);
    int* scnt   = (int*)(sm + CNT_OFF);

    const int tid = threadIdx.x;
    const int rg = (tid >> 5) * 8;         // my 8 rows (warp-owned)
    const int cg = (tid & 31) * 4;         // my 4 codes within chunk
    const int n0 = blockIdx.x * 64;

    if (tid < 64) scnt[tid] = 0;

    // Load resident z tile: Zs[dq][r]
    for (int i = tid; i < 1024; i += 256) {
        int dq = i >> 4, seg = i & 15;
        *(uint4*)&Zs[dq * 64 + seg * 4] =
            *(const uint4*)&g_zq[dq * NR + n0 + seg * 4];
    }
    // Prefetch codebook chunk 0 into registers
    uint4 pre[8];
#pragma unroll
    for (int j = 0; j < 8; j++) {
        int idx = tid * 8 + j;
        int dq = idx >> 5, cs = idx & 31;
        pre[j] = *(const uint4*)&g_cq[dq * KC + cs * 4];
    }

    float zn[8], rm[8];
#pragma unroll
    for (int r = 0; r < 8; r++) {
        zn[r] = g_zn[n0 + rg + r];
        rm[r] = 3.4e38f;
    }

    for (int it = 0; it < 64; it++) {
        // store prefetched chunk
#pragma unroll
        for (int j = 0; j < 8; j++) {
            int idx = tid * 8 + j;
            int dq = idx >> 5, cs = idx & 31;
            *(uint4*)&Es[dq * 128 + cs * 4] = pre[j];
        }
        __syncthreads();

        // prefetch next chunk while computing
        uint4 nxt[8];
        if (it + 1 < 64) {
            const int kn = (it + 1) * 128;
#pragma unroll
            for (int j = 0; j < 8; j++) {
                int idx = tid * 8 + j;
                int dq = idx >> 5, cs = idx & 31;
                nxt[j] = *(const uint4*)&g_cq[dq * KC + kn + cs * 4];
            }
        }

        int acc[8][4];
#pragma unroll
        for (int r = 0; r < 8; r++)
#pragma unroll
            for (int v = 0; v < 4; v++) acc[r][v] = 0;

#pragma unroll 4
        for (int dq = 0; dq < 64; dq++) {
            uint4 z0 = *(const uint4*)&Zs[dq * 64 + rg];       // rows rg..rg+3
            uint4 z1 = *(const uint4*)&Zs[dq * 64 + rg + 4];   // rows rg+4..+7
            uint4 ev = *(const uint4*)&Es[dq * 128 + cg];      // codes cg..cg+3
            const int zw[8] = {(int)z0.x, (int)z0.y, (int)z0.z, (int)z0.w,
                               (int)z1.x, (int)z1.y, (int)z1.z, (int)z1.w};
            const int ew[4] = {(int)ev.x, (int)ev.y, (int)ev.z, (int)ev.w};
#pragma unroll
            for (int r = 0; r < 8; r++) {
                acc[r][0] = __dp4a(zw[r], ew[0], acc[r][0]);
                acc[r][1] = __dp4a(zw[r], ew[1], acc[r][1]);
                acc[r][2] = __dp4a(zw[r], ew[2], acc[r][2]);
                acc[r][3] = __dp4a(zw[r], ew[3], acc[r][3]);
            }
        }

        // ---- two-phase epilogue ----
        const int kb = it * 128 + cg;
        float sv[8][4];
        // Phase A: scores + warp-wide row-min merged into rm BEFORE writes
#pragma unroll
        for (int r = 0; r < 8; r++) {
            float cmin = 3.4e38f;
#pragma unroll
            for (int v = 0; v < 4; v++) {
                sv[r][v] = fmaf((float)acc[r][v], M2INV, zn[r]);
                cmin = fminf(cmin, sv[r][v]);
            }
#pragma unroll
            for (int o = 16; o; o >>= 1)
                cmin = fminf(cmin, __shfl_xor_sync(0xffffffffu, cmin, o));
            rm[r] = fminf(rm[r], cmin);
        }
        // Phase B: collect only within MARGIN of global-so-far row min
#pragma unroll
        for (int r = 0; r < 8; r++) {
            const int row = rg + r;
            const float thr = rm[r] + MARGIN;
#pragma unroll
            for (int v = 0; v < 4; v++) {
                if (sv[r][v] < thr) {
                    int sl = atomicAdd(&scnt[row], 1);
                    if (sl < CAPM) slist[row * CAPM + sl] = kb + v;
                }
            }
        }

#pragma unroll
        for (int j = 0; j < 8; j++) pre[j] = nxt[j];
        __syncthreads();
    }

    if (tid < 64) {
        int cnt = scnt[tid];
        int n = n0 + tid;
        g_cand_cnt[n] = (cnt > CAPM) ? (CAPM + 1) : cnt;
        int m = (cnt < CAPM) ? cnt : CAPM;
        for (int j = 0; j < m; j++) g_cand[n * CAPM + j] = slist[tid * CAPM + j];
    }
}

// ---------------------------------------------------------------------------
// Kernel 4: exact rescue (bit-exact sequential fp32 chain over candidates).
// ---------------------------------------------------------------------------
__global__ __launch_bounds__(64)
void rescue_kernel(float* __restrict__ idxf) {
    __shared__ float zrow[DD];
    __shared__ float rv[64];
    __shared__ int   ri[64];
    const int n = blockIdx.x;
    const int tid = threadIdx.x;

    *(float4*)&zrow[tid * 4] = *(const float4*)&g_zf[n * DD + tid * 4];
    __syncthreads();
    const float zn = g_zn[n];

    float bv = 3.4e38f; int bi = 0x7FFFFFFF;
    int cnt = g_cand_cnt[n];
    if (cnt > CAPM) {
        for (int k = tid; k < KC; k += 64) {
            float acc = 0.f;
            const float4* cb = (const float4*)&g_codebook[k * DD];
#pragma unroll 4
            for (int d4 = 0; d4 < 64; d4++) {
                float4 cc = cb[d4];
                float4 zv = *(const float4*)&zrow[d4 * 4];
                acc = fmaf(zv.x, cc.x, acc); acc = fmaf(zv.y, cc.y, acc);
                acc = fmaf(zv.z, cc.z, acc); acc = fmaf(zv.w, cc.w, acc);
            }
            float s = fmaf(-2.f, acc, zn);
            if (s < bv || (s == bv && k < bi)) { bv = s; bi = k; }
        }
    } else {
        for (int j = tid; j < cnt; j += 64) {
            int k = g_cand[n * CAPM + j];
            float acc = 0.f;
            const float4* cb = (const float4*)&g_codebook[k * DD];
#pragma unroll 4
            for (int d4 = 0; d4 < 64; d4++) {
                float4 cc = cb[d4];
                float4 zv = *(const float4*)&zrow[d4 * 4];
                acc = fmaf(zv.x, cc.x, acc); acc = fmaf(zv.y, cc.y, acc);
                acc = fmaf(zv.z, cc.z, acc); acc = fmaf(zv.w, cc.w, acc);
            }
            float s = fmaf(-2.f, acc, zn);
            if (s < bv || (s == bv && k < bi)) { bv = s; bi = k; }
        }
    }
    rv[tid] = bv; ri[tid] = bi;
    __syncthreads();
    for (int o = 32; o; o >>= 1) {
        if (tid < o) {
            float v = rv[tid + o]; int i2 = ri[tid + o];
            if (v < rv[tid] || (v == rv[tid] && i2 < ri[tid])) {
                rv[tid] = v; ri[tid] = i2;
            }
        }
        __syncthreads();
    }
    if (tid == 0) {
        g_minidx[n] = ri[0];
        if (idxf) idxf[n] = (float)ri[0];
    }
}

// ---------------------------------------------------------------------------
// Kernel 5: gather + straight-through output + squared error partials.
// out = fl(zt + fl(zq - zt)) exactly as the reference.
// ---------------------------------------------------------------------------
__global__ void gather_out(const float* __restrict__ z, float* __restrict__ out) {
    __shared__ float s[256 * 33];
    const int tid = threadIdx.x;
    const int n0 = blockIdx.x * 32;
    const int b = n0 >> 10, hw0 = n0 & 1023;

#pragma unroll 1
    for (int nl = 0; nl < 32; nl++) {
        int ci = g_minidx[n0 + nl];
        s[tid * 33 + nl] = g_codebook[ci * DD + tid];
    }
    __syncthreads();

    float local = 0.f;
    const float* zb = z + b * CHW + hw0;
    float* ob = out + b * CHW + hw0;
    for (int e = tid; e < 32 * DD; e += 256) {
        int c = e >> 5, hl = e & 31;
        float q  = s[c * 33 + hl];
        float zv = zb[c * HW + hl];
        float d  = q - zv;
        ob[c * HW + hl] = zv + d;
        local = fmaf(d, d, local);
    }
    __syncthreads();
    float* red = s;
    red[tid] = local;
    __syncthreads();
    for (int o = 128; o; o >>= 1) {
        if (tid < o) red[tid] += red[tid + o];
        __syncthreads();
    }
    if (tid == 0) g_partials[blockIdx.x] = red[0];
}

// ---------------------------------------------------------------------------
// Kernel 6: final reduction + loss scalars
// ---------------------------------------------------------------------------
__global__ void finalize_kernel(float* __restrict__ outp, int has_scalars) {
    __shared__ float red[512];
    const int tid = threadIdx.x;
    red[tid] = g_partials[tid];
    __syncthreads();
    for (int o = 256; o; o >>= 1) {
        if (tid < o) red[tid] += red[tid + o];
        __syncthreads();
    }
    if (tid == 0 && has_scalars) {
        float mse = red[0] * (1.0f / 4194304.0f);
        float cl  = 0.25f * mse;
        float bl  = mse;
        outp[4194304] = cl + bl;
        outp[4194305] = cl;
        outp[4194306] = bl;
    }
}

// ---------------------------------------------------------------------------
extern "C" void kernel_launch(void* const* d_in, const int* in_sizes, int n_in,
                              void* d_out, int out_size) {
    const float* z   = (const float*)d_in[0];   // [16,256,32,32]
    const float* emb = (const float*)d_in[1];   // [8192,256]
    const float* pw  = (const float*)d_in[2];   // [256,256]
    float* out = (float*)d_out;

    cudaFuncSetAttribute(argmin_dp4a,
                         cudaFuncAttributeMaxDynamicSharedMemorySize, SMEM_DP4A);

    codebook_gemm<<<dim3(4, 128), 256>>>(emb, pw);
    z_prep<<<512, 256>>>(z);

    float* idxf = nullptr;
    if (out_size >= 4194307 + NR) idxf = out + 4194307;

    argmin_dp4a<<<256, 256, SMEM_DP4A>>>();
    rescue_kernel<<<NR, 64>>>(idxf);
    gather_out<<<512, 256>>>(z, out);
    finalize_kernel<<<1, 512>>>(out, (out_size >= 4194307) ? 1 : 0);
}

// round 13
// speedup vs baseline: 20.9704x; 1.8585x over previous
#include <cuda_runtime.h>
#include <cuda_fp16.h>
#include <cstdint>

// Problem constants
#define KC  8192          // number of codes
#define DD  256           // embedding / channel dim
#define NR  16384         // B*H*W rows
#define HW  1024          // H*W
#define CHW (DD * HW)     // per-batch stride in z / out

#define CAPM    32        // candidate list capacity per row
#define MARGIN  4e-4f     // >= ~7x worst-case fp16 score error (~6e-5)

#define ESCALE  8192.0f   // codebook pre-scale (keeps fp16 normal range)
#define SINV    (-2.0f / ESCALE)

// Scratch (static device memory)
__device__ float g_codebook[KC * DD];        // emb @ proj_w^T fp32
__device__ float g_zf[NR * DD];              // z transposed [N][D] fp32
__device__ float g_zn[NR];                   // ||z_n||^2 (fp32 chain)
__device__ int   g_cand[NR * CAPM];          // candidate indices
__device__ int   g_cand_cnt[NR];             // count (>CAPM = overflow)
__device__ int   g_minidx[NR];
__device__ float g_partials[512];

// half2 operands, d-pair-major: [dp 0..127][index]; codebook scaled by ESCALE
__device__ __align__(16) __half2 g_ch2[128 * KC];
__device__ __align__(16) __half2 g_zh2[128 * NR];

// ---------------------------------------------------------------------------
// Kernel 1: codebook = emb @ proj^T (exact fp32 sequential-j chain) +
// fused scaled-half2 transposed pack into g_ch2[dp][k].
// ---------------------------------------------------------------------------
__global__ void codebook_gemm(const float* __restrict__ emb,
                              const float* __restrict__ pw) {
    __shared__ float As[16 * 65];
    __shared__ float Bs[16 * 65];
    const int tid = threadIdx.x;
    const int tx = tid & 15, ty = tid >> 4;
    const int k0 = blockIdx.y * 64;
    const int d0 = blockIdx.x * 64;
    const int rl = tid >> 2;
    const int j4 = (tid & 3) << 2;

    float acc[4][4];
#pragma unroll
    for (int u = 0; u < 4; u++)
#pragma unroll
        for (int v = 0; v < 4; v++) acc[u][v] = 0.f;

    for (int j0 = 0; j0 < DD; j0 += 16) {
        float4 va = *(const float4*)&emb[(k0 + rl) * DD + j0 + j4];
        float4 vb = *(const float4*)&pw[(d0 + rl) * DD + j0 + j4];
        As[(j4 + 0) * 65 + rl] = va.x;  As[(j4 + 1) * 65 + rl] = va.y;
        As[(j4 + 2) * 65 + rl] = va.z;  As[(j4 + 3) * 65 + rl] = va.w;
        Bs[(j4 + 0) * 65 + rl] = vb.x;  Bs[(j4 + 1) * 65 + rl] = vb.y;
        Bs[(j4 + 2) * 65 + rl] = vb.z;  Bs[(j4 + 3) * 65 + rl] = vb.w;
        __syncthreads();
#pragma unroll
        for (int jj = 0; jj < 16; jj++) {
            const float* ap = &As[jj * 65 + ty * 4];
            const float* bp = &Bs[jj * 65 + tx * 4];
            float a0 = ap[0], a1 = ap[1], a2 = ap[2], a3 = ap[3];
            float b0 = bp[0], b1 = bp[1], b2 = bp[2], b3 = bp[3];
            acc[0][0] = fmaf(a0, b0, acc[0][0]); acc[0][1] = fmaf(a0, b1, acc[0][1]);
            acc[0][2] = fmaf(a0, b2, acc[0][2]); acc[0][3] = fmaf(a0, b3, acc[0][3]);
            acc[1][0] = fmaf(a1, b0, acc[1][0]); acc[1][1] = fmaf(a1, b1, acc[1][1]);
            acc[1][2] = fmaf(a1, b2, acc[1][2]); acc[1][3] = fmaf(a1, b3, acc[1][3]);
            acc[2][0] = fmaf(a2, b0, acc[2][0]); acc[2][1] = fmaf(a2, b1, acc[2][1]);
            acc[2][2] = fmaf(a2, b2, acc[2][2]); acc[2][3] = fmaf(a2, b3, acc[2][3]);
            acc[3][0] = fmaf(a3, b0, acc[3][0]); acc[3][1] = fmaf(a3, b1, acc[3][1]);
            acc[3][2] = fmaf(a3, b2, acc[3][2]); acc[3][3] = fmaf(a3, b3, acc[3][3]);
        }
        __syncthreads();
    }
#pragma unroll
    for (int u = 0; u < 4; u++) {
        int k = k0 + ty * 4 + u;
        float4 w = make_float4(acc[u][0], acc[u][1], acc[u][2], acc[u][3]);
        *(float4*)&g_codebook[k * DD + d0 + tx * 4] = w;
        int dp0 = (d0 + tx * 4) >> 1;
        g_ch2[(dp0 + 0) * KC + k] =
            __floats2half2_rn(acc[u][0] * ESCALE, acc[u][1] * ESCALE);
        g_ch2[(dp0 + 1) * KC + k] =
            __floats2half2_rn(acc[u][2] * ESCALE, acc[u][3] * ESCALE);
    }
}

// ---------------------------------------------------------------------------
// Kernel 2: z transpose -> g_zf [N][D] fp32, zn per row (sequential chain),
// fused half2 pair pack into g_zh2[dp][n].
// ---------------------------------------------------------------------------
__global__ void z_prep(const float* __restrict__ z) {
    __shared__ float Zs[256 * 33];
    const int tid = threadIdx.x;
    const int n0 = blockIdx.x * 32;
    const int b = n0 >> 10, hw0 = n0 & 1023;
    const float* zb = z + b * CHW + hw0;

    for (int e = tid; e < 32 * DD; e += 256) {
        int d = e >> 5, m = e & 31;
        Zs[d * 33 + m] = zb[d * HW + m];
    }
    __syncthreads();
    // fp32 transposed copy for rescue
    for (int idx = tid; idx < 32 * DD; idx += 256) {
        int nl = idx >> 8, d = idx & 255;
        g_zf[(n0 + nl) * DD + d] = Zs[d * 33 + nl];
    }
    // half2 pair pack (nl fastest -> coalesced stores)
    for (int idx = tid; idx < 32 * 128; idx += 256) {
        int nl = idx & 31, dp = idx >> 5;
        g_zh2[dp * NR + n0 + nl] =
            __floats2half2_rn(Zs[(2 * dp) * 33 + nl], Zs[(2 * dp + 1) * 33 + nl]);
    }
    if (tid < 32) {
        float s = 0.f;
#pragma unroll 8
        for (int d = 0; d < DD; d++) { float v = Zs[d * 33 + tid]; s = fmaf(v, v, s); }
        g_zn[n0 + tid] = s;
    }
}

// ---------------------------------------------------------------------------
// Kernel 3: HFMA2 distance GEMM + TIGHT two-phase margin candidate collect.
// Block = 64 rows resident (Zh [dp][row] half2, 32KB); 128 chunks of 64
// codes, single-buffer Es with register-prefetch LDG->STS (R2/R12-proven,
// no cp.async). Thread tile 4 rows x 4 codes; per dp: 2x LDS.128 + 16 HFMA2.
// fp16 accumulators merged to fp32 every 32 dp. Epilogue: (A) chunk scores
// -> half-warp row-min merged into rm BEFORE writes, (B) write only scores
// < rm + MARGIN (prevents R9/R11 candidate flooding).
// ---------------------------------------------------------------------------
#define ZH_OFF    0
#define ES_OFF    32768
#define LIST_OFF  65536
#define CNT_OFF   (LIST_OFF + 64 * CAPM * 4)
#define SMEM_H2   (CNT_OFF + 64 * 4)

__global__ __launch_bounds__(256, 2)
void argmin_h2(void) {
    extern __shared__ char sm[];
    __half2* Zh = (__half2*)(sm + ZH_OFF);   // [128 dp][64 rows]
    __half2* Es = (__half2*)(sm + ES_OFF);   // [128 dp][64 codes]
    int* slist  = (int*)(sm + LIST_OFF);
    int* scnt   = (int*)(sm + CNT_OFF);

    const int tid = threadIdx.x;
    const int tx = tid & 15, ty = tid >> 4;  // 16 codes x 16 row-groups
    const int n0 = blockIdx.x * 64;

    if (tid < 64) scnt[tid] = 0;

    // Load resident z tile: Zh[dp][r]  (uint4 = 4 half2)
    for (int i = tid; i < 2048; i += 256) {
        int dp = i >> 4, seg = i & 15;
        *(uint4*)&Zh[dp * 64 + seg * 4] =
            *(const uint4*)&g_zh2[dp * NR + n0 + seg * 4];
    }
    // Prefetch codebook chunk 0 into registers (8 x 16B per thread)
    uint4 pre[8];
#pragma unroll
    for (int j = 0; j < 8; j++) {
        int idx = tid * 8 + j;
        int dp = idx >> 4, seg = idx & 15;
        pre[j] = *(const uint4*)&g_ch2[dp * KC + seg * 4];
    }

    float zn[4], rm[4];
#pragma unroll
    for (int r = 0; r < 4; r++) {
        zn[r] = g_zn[n0 + ty * 4 + r];
        rm[r] = 3.4e38f;
    }

    for (int it = 0; it < 128; it++) {
        // store prefetched chunk
#pragma unroll
        for (int j = 0; j < 8; j++) {
            int idx = tid * 8 + j;
            int dp = idx >> 4, seg = idx & 15;
            *(uint4*)&Es[dp * 64 + seg * 4] = pre[j];
        }
        __syncthreads();

        // prefetch next chunk while computing
        uint4 nxt[8];
        if (it + 1 < 128) {
            const int kn = (it + 1) * 64;
#pragma unroll
            for (int j = 0; j < 8; j++) {
                int idx = tid * 8 + j;
                int dp = idx >> 4, seg = idx & 15;
                nxt[j] = *(const uint4*)&g_ch2[dp * KC + kn + seg * 4];
            }
        }

        const __half2* Zp = Zh + ty * 4;
        const __half2* Ep = Es + tx * 4;

        float c32[4][4];
#pragma unroll
        for (int r = 0; r < 4; r++)
#pragma unroll
            for (int v = 0; v < 4; v++) c32[r][v] = 0.f;

#pragma unroll 1
        for (int o = 0; o < 4; o++) {           // 4 blocks of 32 d-pairs
            __half2 h[4][4];
            const __half2 hz = __floats2half2_rn(0.f, 0.f);
#pragma unroll
            for (int r = 0; r < 4; r++)
#pragma unroll
                for (int v = 0; v < 4; v++) h[r][v] = hz;
#pragma unroll
            for (int d = 0; d < 32; d++) {
                int dp = o * 32 + d;
                float4 zv = *(const float4*)(Zp + dp * 64);
                float4 ev = *(const float4*)(Ep + dp * 64);
                __half2 z0 = *(__half2*)&zv.x, z1 = *(__half2*)&zv.y;
                __half2 z2 = *(__half2*)&zv.z, z3 = *(__half2*)&zv.w;
                __half2 e0 = *(__half2*)&ev.x, e1 = *(__half2*)&ev.y;
                __half2 e2 = *(__half2*)&ev.z, e3 = *(__half2*)&ev.w;
                h[0][0] = __hfma2(z0, e0, h[0][0]); h[0][1] = __hfma2(z0, e1, h[0][1]);
                h[0][2] = __hfma2(z0, e2, h[0][2]); h[0][3] = __hfma2(z0, e3, h[0][3]);
                h[1][0] = __hfma2(z1, e0, h[1][0]); h[1][1] = __hfma2(z1, e1, h[1][1]);
                h[1][2] = __hfma2(z1, e2, h[1][2]); h[1][3] = __hfma2(z1, e3, h[1][3]);
                h[2][0] = __hfma2(z2, e0, h[2][0]); h[2][1] = __hfma2(z2, e1, h[2][1]);
                h[2][2] = __hfma2(z2, e2, h[2][2]); h[2][3] = __hfma2(z2, e3, h[2][3]);
                h[3][0] = __hfma2(z3, e0, h[3][0]); h[3][1] = __hfma2(z3, e1, h[3][1]);
                h[3][2] = __hfma2(z3, e2, h[3][2]); h[3][3] = __hfma2(z3, e3, h[3][3]);
            }
            // fp32 merge
#pragma unroll
            for (int r = 0; r < 4; r++)
#pragma unroll
                for (int v = 0; v < 4; v++)
                    c32[r][v] += __low2float(h[r][v]) + __high2float(h[r][v]);
        }

        // ---- two-phase epilogue ----
        const int kb = it * 64 + tx * 4;
        float sv[4][4];
        // Phase A: scores + half-warp (16-lane) row-min merged into rm
#pragma unroll
        for (int r = 0; r < 4; r++) {
            float cmin = 3.4e38f;
#pragma unroll
            for (int v = 0; v < 4; v++) {
                sv[r][v] = fmaf(c32[r][v], SINV, zn[r]);
                cmin = fminf(cmin, sv[r][v]);
            }
#pragma unroll
            for (int o = 8; o; o >>= 1)   // xor 8,4,2,1: stays in 16-lane half
                cmin = fminf(cmin, __shfl_xor_sync(0xffffffffu, cmin, o));
            rm[r] = fminf(rm[r], cmin);
        }
        // Phase B: collect only within MARGIN of global-so-far row min
#pragma unroll
        for (int r = 0; r < 4; r++) {
            const int row = ty * 4 + r;
            const float thr = rm[r] + MARGIN;
#pragma unroll
            for (int v = 0; v < 4; v++) {
                if (sv[r][v] < thr) {
                    int sl = atomicAdd(&scnt[row], 1);
                    if (sl < CAPM) slist[row * CAPM + sl] = kb + v;
                }
            }
        }

#pragma unroll
        for (int j = 0; j < 8; j++) pre[j] = nxt[j];
        __syncthreads();
    }

    if (tid < 64) {
        int cnt = scnt[tid];
        int n = n0 + tid;
        g_cand_cnt[n] = (cnt > CAPM) ? (CAPM + 1) : cnt;
        int m = (cnt < CAPM) ? cnt : CAPM;
        for (int j = 0; j < m; j++) g_cand[n * CAPM + j] = slist[tid * CAPM + j];
    }
}

// ---------------------------------------------------------------------------
// Kernel 4: exact rescue (bit-exact sequential fp32 chain over candidates).
// Validated: rel_err 0.0 in R7/R9/R11/R12.
// ---------------------------------------------------------------------------
__global__ __launch_bounds__(64)
void rescue_kernel(float* __restrict__ idxf) {
    __shared__ float zrow[DD];
    __shared__ float rv[64];
    __shared__ int   ri[64];
    const int n = blockIdx.x;
    const int tid = threadIdx.x;

    *(float4*)&zrow[tid * 4] = *(const float4*)&g_zf[n * DD + tid * 4];
    __syncthreads();
    const float zn = g_zn[n];

    float bv = 3.4e38f; int bi = 0x7FFFFFFF;
    int cnt = g_cand_cnt[n];
    if (cnt > CAPM) {
        for (int k = tid; k < KC; k += 64) {
            float acc = 0.f;
            const float4* cb = (const float4*)&g_codebook[k * DD];
#pragma unroll 4
            for (int d4 = 0; d4 < 64; d4++) {
                float4 cc = cb[d4];
                float4 zv = *(const float4*)&zrow[d4 * 4];
                acc = fmaf(zv.x, cc.x, acc); acc = fmaf(zv.y, cc.y, acc);
                acc = fmaf(zv.z, cc.z, acc); acc = fmaf(zv.w, cc.w, acc);
            }
            float s = fmaf(-2.f, acc, zn);
            if (s < bv || (s == bv && k < bi)) { bv = s; bi = k; }
        }
    } else {
        for (int j = tid; j < cnt; j += 64) {
            int k = g_cand[n * CAPM + j];
            float acc = 0.f;
            const float4* cb = (const float4*)&g_codebook[k * DD];
#pragma unroll 4
            for (int d4 = 0; d4 < 64; d4++) {
                float4 cc = cb[d4];
                float4 zv = *(const float4*)&zrow[d4 * 4];
                acc = fmaf(zv.x, cc.x, acc); acc = fmaf(zv.y, cc.y, acc);
                acc = fmaf(zv.z, cc.z, acc); acc = fmaf(zv.w, cc.w, acc);
            }
            float s = fmaf(-2.f, acc, zn);
            if (s < bv || (s == bv && k < bi)) { bv = s; bi = k; }
        }
    }
    rv[tid] = bv; ri[tid] = bi;
    __syncthreads();
    for (int o = 32; o; o >>= 1) {
        if (tid < o) {
            float v = rv[tid + o]; int i2 = ri[tid + o];
            if (v < rv[tid] || (v == rv[tid] && i2 < ri[tid])) {
                rv[tid] = v; ri[tid] = i2;
            }
        }
        __syncthreads();
    }
    if (tid == 0) {
        g_minidx[n] = ri[0];
        if (idxf) idxf[n] = (float)ri[0];
    }
}

// ---------------------------------------------------------------------------
// Kernel 5: gather + straight-through output + squared error partials.
// out = fl(zt + fl(zq - zt)) exactly as the reference.
// ---------------------------------------------------------------------------
__global__ void gather_out(const float* __restrict__ z, float* __restrict__ out) {
    __shared__ float s[256 * 33];
    const int tid = threadIdx.x;
    const int n0 = blockIdx.x * 32;
    const int b = n0 >> 10, hw0 = n0 & 1023;

#pragma unroll 1
    for (int nl = 0; nl < 32; nl++) {
        int ci = g_minidx[n0 + nl];
        s[tid * 33 + nl] = g_codebook[ci * DD + tid];
    }
    __syncthreads();

    float local = 0.f;
    const float* zb = z + b * CHW + hw0;
    float* ob = out + b * CHW + hw0;
    for (int e = tid; e < 32 * DD; e += 256) {
        int c = e >> 5, hl = e & 31;
        float q  = s[c * 33 + hl];
        float zv = zb[c * HW + hl];
        float d  = q - zv;
        ob[c * HW + hl] = zv + d;
        local = fmaf(d, d, local);
    }
    __syncthreads();
    float* red = s;
    red[tid] = local;
    __syncthreads();
    for (int o = 128; o; o >>= 1) {
        if (tid < o) red[tid] += red[tid + o];
        __syncthreads();
    }
    if (tid == 0) g_partials[blockIdx.x] = red[0];
}

// ---------------------------------------------------------------------------
// Kernel 6: final reduction + loss scalars
// ---------------------------------------------------------------------------
__global__ void finalize_kernel(float* __restrict__ outp, int has_scalars) {
    __shared__ float red[512];
    const int tid = threadIdx.x;
    red[tid] = g_partials[tid];
    __syncthreads();
    for (int o = 256; o; o >>= 1) {
        if (tid < o) red[tid] += red[tid + o];
        __syncthreads();
    }
    if (tid == 0 && has_scalars) {
        float mse = red[0] * (1.0f / 4194304.0f);
        float cl  = 0.25f * mse;
        float bl  = mse;
        outp[4194304] = cl + bl;
        outp[4194305] = cl;
        outp[4194306] = bl;
    }
}

// ---------------------------------------------------------------------------
extern "C" void kernel_launch(void* const* d_in, const int* in_sizes, int n_in,
                              void* d_out, int out_size) {
    const float* z   = (const float*)d_in[0];   // [16,256,32,32]
    const float* emb = (const float*)d_in[1];   // [8192,256]
    const float* pw  = (const float*)d_in[2];   // [256,256]
    float* out = (float*)d_out;

    cudaFuncSetAttribute(argmin_h2,
                         cudaFuncAttributeMaxDynamicSharedMemorySize, SMEM_H2);

    codebook_gemm<<<dim3(4, 128), 256>>>(emb, pw);
    z_prep<<<512, 256>>>(z);

    float* idxf = nullptr;
    if (out_size >= 4194307 + NR) idxf = out + 4194307;

    argmin_h2<<<256, 256, SMEM_H2>>>();
    rescue_kernel<<<NR, 64>>>(idxf);
    gather_out<<<512, 256>>>(z, out);
    finalize_kernel<<<1, 512>>>(out, (out_size >= 4194307) ? 1 : 0);
}